// round 16
// baseline (speedup 1.0000x reference)
#include <cuda_runtime.h>

// PCNN recurrence B=32, T=64, L=8192 — time-chunked warp-autonomous trapezoids,
// packed f32x2 math + MUFU tanh sigmoid + depth-3 register x-prefetch.
//
// R16: grid balanced to 288 blocks (9 segs x 32 rows, SEG=912; 140 SMs carry 2
// blocks, 8 carry 1 -> 2.7% imbalance vs 16% at 256 blocks). SEG no longer
// divides L: the right overhang past 8192 is handled identically to the left
// edge (y forced 0 outside [0,L), stores predicated, x clamped).
//
// Block owns SEG of one batch row, computes region 1088 = 96*11+32 (halo 88 >=
// 64+16 required). T split into 4 chunks of TC=16; each warp holds 128 y elems
// in registers (4/thread), 2 shuffles/step; cone shrinks 1/step so central 96
// stay exact; y re-exchanged through SMEM at chunk boundaries only.

#define Tn   64
#define Ln   8192
#define Bn   32
#define SEG  912
#define NSEG 9                  // ceil(8192/912): 9*912 = 8208 covers L
#define TC   16
#define NW   11
#define WR   (96 * NW + 32)     // 1088 region cells
#define NTH  (NW * 32)          // 352

typedef unsigned long long u64;

__device__ __forceinline__ u64 pk(float lo, float hi) {
    u64 r; asm("mov.b64 %0,{%1,%2};" : "=l"(r) : "f"(lo), "f"(hi)); return r;
}
__device__ __forceinline__ void upk(u64 v, float& lo, float& hi) {
    asm("mov.b64 {%0,%1},%2;" : "=f"(lo), "=f"(hi) : "l"(v));
}
__device__ __forceinline__ u64 fma2(u64 a, u64 b, u64 c) {
    u64 d; asm("fma.rn.f32x2 %0,%1,%2,%3;" : "=l"(d) : "l"(a), "l"(b), "l"(c)); return d;
}
__device__ __forceinline__ u64 add2(u64 a, u64 b) {
    u64 d; asm("add.rn.f32x2 %0,%1,%2;" : "=l"(d) : "l"(a), "l"(b)); return d;
}
__device__ __forceinline__ u64 mul2(u64 a, u64 b) {
    u64 d; asm("mul.rn.f32x2 %0,%1,%2;" : "=l"(d) : "l"(a), "l"(b)); return d;
}
__device__ __forceinline__ float tanhap(float z) {
    float r; asm("tanh.approx.f32 %0,%1;" : "=f"(r) : "f"(z)); return r;
}

__global__ __launch_bounds__(NTH, 2)
void pcnn_kernel(const float* __restrict__ x,
                 const float* __restrict__ w,
                 float* __restrict__ out)
{
    const int tid  = threadIdx.x;
    const int warp = tid >> 5;
    const int lane = tid & 31;
    const int b    = blockIdx.y;
    const int s0   = blockIdx.x * SEG;
    const int off  = 96 * warp + 4 * lane;   // region-rel base of 4 elems
    const int q0   = s0 - 88 + off;          // absolute position of elem 0

    const float w0s = __ldg(&w[0]);
    const float w1s = __ldg(&w[1]);
    const float w2s = __ldg(&w[2]);

    const u64 W0 = pk(w0s, w0s), W1 = pk(w1s, w1s), W2 = pk(w2s, w2s);
    const u64 DF = pk(0.90483741803595952f, 0.90483741803595952f);  // exp(-0.1)
    const u64 DL = pk(0.36787944117144233f, 0.36787944117144233f);  // exp(-1)
    const u64 Q  = pk(0.25f, 0.25f);
    const u64 H  = pk(0.5f, 0.5f);
    const u64 NVH = pk(-5.0f, -5.0f);        // -(V_E)/2

    const bool inL  = (q0 >= 0) && (q0 < Ln);   // inside [0,L): real cells
    const bool own  = (lane >= 4) && (lane < 28);
    const bool pOut = own && (q0 >= s0) && (q0 < s0 + SEG) && (q0 < Ln);

    // clamped x address (always safe to load; garbage only feeds !inL lanes)
    const int qc = q0 < 0 ? 0 : (q0 > Ln - 4 ? Ln - 4 : q0);
    const ulonglong2* xrow = (const ulonglong2*)(x + (size_t)(b * Tn) * Ln) + (qc >> 2);
    float4*           op   = (float4*)(out + (size_t)(b * Tn) * Ln) + (q0 >> 2);

    __shared__ float ys[WR];
    if (tid < WR / 4) ((float4*)ys)[tid] = make_float4(0.f, 0.f, 0.f, 0.f);

    u64 F01 = 0, F23 = 0, L01 = 0, L23 = 0;
    u64 E01 = pk(-5.f, -5.f), E23 = pk(-5.f, -5.f);   // En = -e/2, e0 = 10
    u64 Y01 = 0, Y23 = 0;

    // register pipeline: rows t, t+1, t+2 in flight (issue distance 3)
    ulonglong2 xv  = __ldg(xrow);                         // row 0
    ulonglong2 xn1 = __ldg(xrow + (size_t)1 * (Ln / 4));  // row 1
    ulonglong2 xn2 = __ldg(xrow + (size_t)2 * (Ln / 4));  // row 2

    __syncthreads();   // ys init visible

    int t = 0;
#pragma unroll 1
    for (int c = 0; c < Tn / TC; ++c) {
        // chunk start: reload full 128-wide warp region from smem
        {
            ulonglong2 yv = *(const ulonglong2*)&ys[off];
            Y01 = yv.x; Y23 = yv.y;
        }
        __syncthreads();

#pragma unroll
        for (int s = 0; s < TC; ++s) {
            // rotate pipeline; issue row (t+3)&63 (wrapped rows 0..2 at the
            // tail land in buffers that are never consumed)
            const ulonglong2 xc = xv;      // row t (consumed this step)
            xv = xn1; xn1 = xn2;
            xn2 = __ldg(xrow + (size_t)((t + 3) & 63) * (Ln / 4));

            float y0, y1, y2, y3;
            upk(Y01, y0, y1); upk(Y23, y2, y3);
            const float yl = __shfl_up_sync(0xffffffffu, y3, 1);   // lane0 garbage: cone-safe
            const float yr = __shfl_down_sync(0xffffffffu, y0, 1); // lane31 garbage: cone-safe

            const u64 A = pk(yl, y0);
            const u64 B = pk(y1, y2);       // shared: yp of pair01, ym of pair23
            const u64 C = pk(y3, yr);

            // f = df*f + x + (w0*ym + w1*y + w2*yp)
            const u64 cv0 = fma2(W0, A, fma2(W1, Y01, mul2(W2, B)));
            const u64 cv1 = fma2(W0, B, fma2(W1, Y23, mul2(W2, C)));
            F01 = add2(fma2(DF, F01, xc.x), cv0);
            F23 = add2(fma2(DF, F23, xc.y), cv1);

            // l = dl*l + ym + yp
            L01 = fma2(DL, L01, add2(A, B));
            L23 = fma2(DL, L23, add2(B, C));

            // u/2 = f * (0.25*l + 0.5)
            const u64 U0 = mul2(F01, fma2(Q, L01, H));
            const u64 U1 = mul2(F23, fma2(Q, L23, H));

            // En = de*En - 5*y   (En = -e/2)
            E01 = fma2(DL, E01, mul2(NVH, Y01));
            E23 = fma2(DL, E23, mul2(NVH, Y23));

            // z/2 = u/2 + En ;  y = 0.5 + 0.5*tanh(z/2)
            float z0, z1, z2, z3;
            upk(add2(U0, E01), z0, z1);
            upk(add2(U1, E23), z2, z3);
            Y01 = fma2(H, pk(tanhap(z0), tanhap(z1)), H);
            Y23 = fma2(H, pk(tanhap(z2), tanhap(z3)), H);

            // positions outside [0,L) emulate the zero pad
            if (!inL) { Y01 = 0; Y23 = 0; }

            if (pOut) {
                float o0, o1, o2, o3;
                upk(Y01, o0, o1); upk(Y23, o2, o3);
                __stcs(op, make_float4(o0, o1, o2, o3));   // streaming store
            }
            op += (Ln / 4);

            ++t;
        }

        // chunk end: publish owned 96 (lanes 4..27)
        if (own) { ulonglong2 o; o.x = Y01; o.y = Y23; *(ulonglong2*)&ys[off] = o; }
        __syncthreads();
    }
}

extern "C" void kernel_launch(void* const* d_in, const int* in_sizes, int n_in,
                              void* d_out, int out_size)
{
    const float* x = (const float*)d_in[0];   // [32, 64, 8192] f32
    const float* w = (const float*)d_in[1];   // [3] f32
    float* out = (float*)d_out;               // [32, 64, 8192] f32

    dim3 grid(NSEG, Bn);   // (9, 32) = 288 blocks of 352 threads
    pcnn_kernel<<<grid, NTH>>>(x, w, out);
}